// round 8
// baseline (speedup 1.0000x reference)
#include <cuda_runtime.h>
#include <math.h>

// Problem constants (match reference)
#define NQ   4096     // NUM_Q
#define SQ   256      // MAX_STEP
#define NB   64       // BATCH
#define ROWW (2 * NQ) // 8192 floats per batch row
#define NROWS (NB * (SQ - 1))   // 16320 scanned rows (s=1..255)

#define SCAN_BLOCKS (148 * 8)   // one full wave of persistent blocks
#define SCAN_THREADS 256

// Scratch (no device allocation allowed). Zero-initialized at module load;
// the last per_batch block resets the counters for the next graph replay.
__device__ int   g_row  = 0;        // work-queue head for scan_rows
__device__ int   g_done = 0;        // completion ticket for per_batch
__device__ int   g_code[NB * SQ];   // per (b,s): (a<<12)|q_idx, or -1 if padded
__device__ float g_partial[NB];     // per-student loss

// ---------------------------------------------------------------------------
// Phase 1: persistent warp-per-row scan with atomic work stealing.
// Each warp pulls a row id, streams the row in 2KB super-chunks (4 coalesced
// 512B segments, MLP=4) and early-exits via ballot. Warp-granular balancing
// keeps occupancy flat (no CTA-retirement max-of-8-warps effect).
// ---------------------------------------------------------------------------
__global__ __launch_bounds__(SCAN_THREADS) void scan_rows(const float* __restrict__ batch) {
    int lane = threadIdx.x & 31;

    for (;;) {
        int r;
        if (lane == 0) r = atomicAdd(&g_row, 1);
        r = __shfl_sync(0xffffffffu, r, 0);
        if (r >= NROWS) break;

        int b = r / (SQ - 1);
        int s = 1 + (r % (SQ - 1));     // row 0 is never used by the reference
        const float4* row =
            (const float4*)(batch + (size_t)(b * SQ + s) * ROWW);

        int local = -1;                 // float position of nonzero (if in my lanes)
        #pragma unroll 1
        for (int c = 0; c < 16; ++c) {  // 16 x 2KB super-chunks per row
            float4 v0 = row[c * 128 +   0 + lane];
            float4 v1 = row[c * 128 +  32 + lane];
            float4 v2 = row[c * 128 +  64 + lane];
            float4 v3 = row[c * 128 +  96 + lane];

            int b0 = (c * 128 +   0 + lane) * 4;
            int b1 = (c * 128 +  32 + lane) * 4;
            int b2 = (c * 128 +  64 + lane) * 4;
            int b3 = (c * 128 +  96 + lane) * 4;
            if (v0.x != 0.0f) local = b0 + 0;
            if (v0.y != 0.0f) local = b0 + 1;
            if (v0.z != 0.0f) local = b0 + 2;
            if (v0.w != 0.0f) local = b0 + 3;
            if (v1.x != 0.0f) local = b1 + 0;
            if (v1.y != 0.0f) local = b1 + 1;
            if (v1.z != 0.0f) local = b1 + 2;
            if (v1.w != 0.0f) local = b1 + 3;
            if (v2.x != 0.0f) local = b2 + 0;
            if (v2.y != 0.0f) local = b2 + 1;
            if (v2.z != 0.0f) local = b2 + 2;
            if (v2.w != 0.0f) local = b2 + 3;
            if (v3.x != 0.0f) local = b3 + 0;
            if (v3.y != 0.0f) local = b3 + 1;
            if (v3.z != 0.0f) local = b3 + 2;
            if (v3.w != 0.0f) local = b3 + 3;

            if (__ballot_sync(0xffffffffu, local >= 0)) break;  // warp-uniform
        }

        // warp max-reduce: at most one lane holds a value >= 0
        int m = local;
        #pragma unroll
        for (int off = 16; off; off >>= 1)
            m = max(m, __shfl_xor_sync(0xffffffffu, m, off));

        if (lane == 0) {
            int code = -1;
            if (m >= 0) {
                int a = (m < NQ) ? 1 : 0;   // first half = answered correctly
                code = (a << 12) | (m & (NQ - 1));
            }
            g_code[b * SQ + s] = code;
        }
    }
}

// ---------------------------------------------------------------------------
// Phase 2 (+fused finalize): one block per student. Gather pred, BCE, trim
// index, per-b loss. The last block to finish folds the 64 partials into
// d_out and resets the counters for the next graph replay.
// ---------------------------------------------------------------------------
__global__ __launch_bounds__(256) void per_batch(const float* __restrict__ pred,
                                                 const float* __restrict__ target_q,
                                                 const float* __restrict__ target_label,
                                                 float* __restrict__ out) {
    int b = blockIdx.x;
    int t = threadIdx.x;                 // s index for t < SQ-1

    float bce = 0.0f;
    int   idx = 1 << 20;                 // sentinel for min-reduce
    if (t < SQ - 1) {
        int code = g_code[b * SQ + t + 1];
        if (code >= 0) {
            float p = pred[(size_t)(b * SQ + t) * NQ + (code & (NQ - 1))];
            float a = (float)((code >> 12) & 1);
            float lp  = fmaxf(logf(p),    -100.0f);
            float l1p = fmaxf(log1pf(-p), -100.0f);
            bce = -(a * lp + (1.0f - a) * l1p);
            idx = t;                     // p > 0 guaranteed (pred in (0.01,0.99))
        }
        // padded (code<0): p=0, a=0  ->  BCE == 0 (matches ref)
    }

    // block reduce: sum(bce), min(idx) — fixed tree, deterministic
    #pragma unroll
    for (int off = 16; off; off >>= 1) {
        bce += __shfl_xor_sync(0xffffffffu, bce, off);
        idx  = min(idx, __shfl_xor_sync(0xffffffffu, idx, off));
    }
    __shared__ float ssum[8];
    __shared__ int   smin[8];
    __shared__ int   s_last;
    if ((t & 31) == 0) { ssum[t >> 5] = bce; smin[t >> 5] = idx; }
    __syncthreads();
    if (t == 0) {
        float total = ssum[0];
        int   im    = smin[0];
        #pragma unroll
        for (int w = 1; w < 8; ++w) { total += ssum[w]; im = min(im, smin[w]); }
        if (im >= SQ - 1) im = 0;        // argmax of all-False returns 0 (ref)

        float p = target_q[b];           // target_q is [B,1]
        float a = target_label[b];
        float tail = -(a * fmaxf(logf(p), -100.0f) +
                       (1.0f - a) * fmaxf(log1pf(-p), -100.0f));
        float n = (float)(SQ - im);      // (S-1) - i + 1
        g_partial[b] = (total + tail) / n;

        __threadfence();                 // publish g_partial[b] before ticket
        int ticket = atomicAdd(&g_done, 1);
        s_last = (ticket == NB - 1) ? 1 : 0;
    }
    __syncthreads();

    if (s_last && t < 32) {
        __threadfence();                 // acquire: see all g_partial writes
        float v = g_partial[t] + g_partial[t + 32];
        #pragma unroll
        for (int off = 16; off; off >>= 1)
            v += __shfl_xor_sync(0xffffffffu, v, off);
        if (t == 0) {
            out[0] = v;
            g_done = 0;                  // reset for next graph replay
            g_row  = 0;
        }
    }
}

// ---------------------------------------------------------------------------
extern "C" void kernel_launch(void* const* d_in, const int* in_sizes, int n_in,
                              void* d_out, int out_size) {
    const float *pred = nullptr, *batch = nullptr, *tq = nullptr, *tl = nullptr;
    for (int i = 0; i < n_in; ++i) {
        long sz = in_sizes[i];
        if (sz == (long)NB * SQ * NQ)          pred  = (const float*)d_in[i];
        else if (sz == (long)NB * SQ * ROWW)   batch = (const float*)d_in[i];
        else if (sz == NB) {                    // dict order: target_q then target_label
            if (!tq) tq = (const float*)d_in[i];
            else     tl = (const float*)d_in[i];
        }
    }

    scan_rows<<<SCAN_BLOCKS, SCAN_THREADS>>>(batch);
    per_batch<<<NB, 256>>>(pred, tq, tl, (float*)d_out);
}

// round 10
// speedup vs baseline: 1.1054x; 1.1054x over previous
#include <cuda_runtime.h>
#include <math.h>

// Problem constants (match reference)
#define NQ   4096     // NUM_Q
#define SQ   256      // MAX_STEP
#define NB   64       // BATCH
#define ROWW (2 * NQ) // 8192 floats per batch row
#define NROWS (NB * (SQ - 1))   // 16320 scanned rows (s=1..255)

// Scratch (no device allocation allowed)
__device__ int   g_code[NB * SQ];   // per (b,s): (a<<12)|q_idx, or -1 if padded row
__device__ float g_partial[NB];     // per-student loss

// ---------------------------------------------------------------------------
// Phase 1: ONE WARP = ONE BLOCK = ONE ROW.
// 32-thread blocks make CTA retirement per-row, so finished warps release
// their slot immediately and the HW scheduler back-fills — zero-cost work
// balancing (no atomics, no squatting). Each step reads a 2KB super-chunk
// (4 coalesced 512B segments, MLP=4) and early-exits via ballot.
// Expected 7.7/16 chunks => ~15.4KB per 32KB row => ~251MB DRAM traffic.
// ---------------------------------------------------------------------------
__global__ __launch_bounds__(32) void scan_rows(const float* __restrict__ batch) {
    int lane = threadIdx.x;             // 0..31
    int r    = blockIdx.x;              // row id 0..NROWS-1
    int b = r / (SQ - 1);
    int s = 1 + (r % (SQ - 1));         // row 0 is never used by the reference
    const float4* row =
        (const float4*)(batch + (size_t)(b * SQ + s) * ROWW);

    int local = -1;                     // float position of nonzero (if in my lanes)
    #pragma unroll 1
    for (int c = 0; c < 16; ++c) {      // 16 x 2KB super-chunks per row
        // 4 independent 512B segments -> 4 outstanding loads per lane
        float4 v0 = row[c * 128 +   0 + lane];
        float4 v1 = row[c * 128 +  32 + lane];
        float4 v2 = row[c * 128 +  64 + lane];
        float4 v3 = row[c * 128 +  96 + lane];

        int b0 = (c * 128 +   0 + lane) * 4;
        int b1 = (c * 128 +  32 + lane) * 4;
        int b2 = (c * 128 +  64 + lane) * 4;
        int b3 = (c * 128 +  96 + lane) * 4;
        if (v0.x != 0.0f) local = b0 + 0;
        if (v0.y != 0.0f) local = b0 + 1;
        if (v0.z != 0.0f) local = b0 + 2;
        if (v0.w != 0.0f) local = b0 + 3;
        if (v1.x != 0.0f) local = b1 + 0;
        if (v1.y != 0.0f) local = b1 + 1;
        if (v1.z != 0.0f) local = b1 + 2;
        if (v1.w != 0.0f) local = b1 + 3;
        if (v2.x != 0.0f) local = b2 + 0;
        if (v2.y != 0.0f) local = b2 + 1;
        if (v2.z != 0.0f) local = b2 + 2;
        if (v2.w != 0.0f) local = b2 + 3;
        if (v3.x != 0.0f) local = b3 + 0;
        if (v3.y != 0.0f) local = b3 + 1;
        if (v3.w != 0.0f) local = b3 + 3;
        if (v3.z != 0.0f) local = b3 + 2;

        if (__ballot_sync(0xffffffffu, local >= 0)) break;  // warp-uniform exit
    }

    // warp max-reduce: at most one lane holds a value >= 0
    #pragma unroll
    for (int off = 16; off; off >>= 1)
        local = max(local, __shfl_xor_sync(0xffffffffu, local, off));

    if (lane == 0) {
        int code = -1;
        if (local >= 0) {
            int a = (local < NQ) ? 1 : 0;   // first half = answered correctly
            code = (a << 12) | (local & (NQ - 1));
        }
        g_code[b * SQ + s] = code;
    }
}

// ---------------------------------------------------------------------------
// Phase 2: one block per student. Gather pred, BCE, trim index, per-b loss.
// ---------------------------------------------------------------------------
__global__ __launch_bounds__(256) void per_batch(const float* __restrict__ pred,
                                                 const float* __restrict__ target_q,
                                                 const float* __restrict__ target_label) {
    int b = blockIdx.x;
    int t = threadIdx.x;                 // s index for t < SQ-1

    float bce = 0.0f;
    int   idx = 1 << 20;                 // sentinel for min-reduce
    if (t < SQ - 1) {
        int code = g_code[b * SQ + t + 1];
        if (code >= 0) {
            float p = pred[(size_t)(b * SQ + t) * NQ + (code & (NQ - 1))];
            float a = (float)((code >> 12) & 1);
            float lp  = fmaxf(logf(p),    -100.0f);
            float l1p = fmaxf(log1pf(-p), -100.0f);
            bce = -(a * lp + (1.0f - a) * l1p);
            idx = t;                     // p > 0 guaranteed (pred in (0.01,0.99))
        }
        // padded (code<0): p=0, a=0  ->  BCE == 0, contributes nothing (matches ref)
    }

    // block reduce: sum(bce), min(idx) — fixed tree, deterministic
    #pragma unroll
    for (int off = 16; off; off >>= 1) {
        bce += __shfl_xor_sync(0xffffffffu, bce, off);
        idx  = min(idx, __shfl_xor_sync(0xffffffffu, idx, off));
    }
    __shared__ float ssum[8];
    __shared__ int   smin[8];
    if ((t & 31) == 0) { ssum[t >> 5] = bce; smin[t >> 5] = idx; }
    __syncthreads();
    if (t == 0) {
        float total = ssum[0];
        int   im    = smin[0];
        #pragma unroll
        for (int w = 1; w < 8; ++w) { total += ssum[w]; im = min(im, smin[w]); }
        if (im >= SQ - 1) im = 0;        // argmax of all-False returns 0 (ref semantics)

        float p = target_q[b];           // target_q is [B,1]
        float a = target_label[b];
        float tail = -(a * fmaxf(logf(p), -100.0f) +
                       (1.0f - a) * fmaxf(log1pf(-p), -100.0f));
        float n = (float)(SQ - im);      // (S-1) - i + 1
        g_partial[b] = (total + tail) / n;
    }
}

// ---------------------------------------------------------------------------
// Phase 3: fold 64 partials into the scalar output.
// ---------------------------------------------------------------------------
__global__ void final_sum(float* __restrict__ out) {
    int t = threadIdx.x;                 // 32 threads
    float v = g_partial[t] + g_partial[t + 32];
    #pragma unroll
    for (int off = 16; off; off >>= 1)
        v += __shfl_xor_sync(0xffffffffu, v, off);
    if (t == 0) out[0] = v;
}

// ---------------------------------------------------------------------------
extern "C" void kernel_launch(void* const* d_in, const int* in_sizes, int n_in,
                              void* d_out, int out_size) {
    const float *pred = nullptr, *batch = nullptr, *tq = nullptr, *tl = nullptr;
    for (int i = 0; i < n_in; ++i) {
        long sz = in_sizes[i];
        if (sz == (long)NB * SQ * NQ)          pred  = (const float*)d_in[i];
        else if (sz == (long)NB * SQ * ROWW)   batch = (const float*)d_in[i];
        else if (sz == NB) {                    // dict order: target_q then target_label
            if (!tq) tq = (const float*)d_in[i];
            else     tl = (const float*)d_in[i];
        }
    }

    scan_rows<<<NROWS, 32>>>(batch);
    per_batch<<<NB, 256>>>(pred, tq, tl);
    final_sum<<<1, 32>>>((float*)d_out);
}